// round 5
// baseline (speedup 1.0000x reference)
#include <cuda_runtime.h>
#include <cuda_fp16.h>
#include <cstdint>

// Block-sparse batched linear (sm_103 family-safe: mma.sync + ldmatrix):
//   Y[i] = sum_{k: i_idx[k]==i} ( X[j_idx[k]] @ W[k] + b[k] )
// Prep: X -> fp16; W -> transposed [n][k] fp16.
// Main: CTA 128x256 (full output width), 512 threads (16 warps, 2x8 grid,
// 64x32 warp tiles), single-pass fp16 mma.sync.m16n8k16 w/ f32 accum,
// ldmatrix.x4 feeds, 6-stage cp.async pipeline, 1 CTA/SM.

namespace {

constexpr int NBLK   = 12;
constexpr int DDIM   = 256;
constexpr int BATCHN = 8192;
constexpr int NACT   = 48;

constexpr int BM = 128;
constexpr int BN = 256;
constexpr int BK = 32;
constexpr int NCH = 32;          // 4 active blocks * 8 k-chunks
constexpr int NSTG = 6;
constexpr int THREADS = 512;

constexpr uint32_t ROWB  = 80;            // 64B data + 16B pad per 32-elem row
constexpr uint32_t A_SZ  = 128 * ROWB;    // 10240 B
constexpr uint32_t B_SZ  = 256 * ROWB;    // 20480 B
constexpr uint32_t OFF_A = 0;
constexpr uint32_t OFF_B = A_SZ;
constexpr uint32_t STAGE_BYTES = A_SZ + B_SZ;              // 30720
constexpr uint32_t SM_BIAS     = NSTG * STAGE_BYTES;       // 184320
constexpr uint32_t SMEM_TOTAL  = SM_BIAS + 256 * 4;        // 185344

// ---- device scratch (static; no runtime allocation) ----
__device__ __half g_Xf[(size_t)NBLK * BATCHN * DDIM];
__device__ __half g_Wtf[(size_t)NACT * DDIM * DDIM];   // [blk][n][k]

// ---------------- helpers ----------------
__device__ __forceinline__ uint32_t smem_u32(const void* p) {
    uint32_t a;
    asm("{ .reg .u64 t; cvta.to.shared.u64 t, %1; cvt.u32.u64 %0, t; }"
        : "=r"(a) : "l"(p));
    return a;
}
__device__ __forceinline__ void cp16(uint32_t dst, const void* src) {
    asm volatile("cp.async.cg.shared.global [%0], [%1], 16;\n" :: "r"(dst), "l"(src));
}
__device__ __forceinline__ void cp_commit() { asm volatile("cp.async.commit_group;\n"); }
template <int N>
__device__ __forceinline__ void cp_wait() { asm volatile("cp.async.wait_group %0;\n" :: "n"(N)); }

__device__ __forceinline__ void ldsm4(uint32_t r[4], uint32_t addr) {
    asm volatile("ldmatrix.sync.aligned.m8n8.x4.shared.b16 {%0,%1,%2,%3}, [%4];"
                 : "=r"(r[0]), "=r"(r[1]), "=r"(r[2]), "=r"(r[3]) : "r"(addr));
}
__device__ __forceinline__ void mma_f16(float d[4], const uint32_t a[4],
                                        uint32_t b0, uint32_t b1) {
    asm volatile(
        "mma.sync.aligned.m16n8k16.row.col.f32.f16.f16.f32 "
        "{%0,%1,%2,%3}, {%4,%5,%6,%7}, {%8,%9}, {%0,%1,%2,%3};\n"
        : "+f"(d[0]), "+f"(d[1]), "+f"(d[2]), "+f"(d[3])
        : "r"(a[0]), "r"(a[1]), "r"(a[2]), "r"(a[3]), "r"(b0), "r"(b1));
}

// ---------------- prep kernels ----------------
__global__ void __launch_bounds__(256) conv_x_kernel(const float* __restrict__ X) {
    size_t i = (size_t)blockIdx.x * blockDim.x + threadIdx.x;  // float4 slot
    const float4 v = reinterpret_cast<const float4*>(X)[i];
    __half2 p0 = __floats2half2_rn(v.x, v.y);
    __half2 p1 = __floats2half2_rn(v.z, v.w);
    reinterpret_cast<uint2*>(g_Xf)[i] =
        make_uint2(*reinterpret_cast<uint32_t*>(&p0), *reinterpret_cast<uint32_t*>(&p1));
}

__global__ void __launch_bounds__(1024) conv_w_kernel(const float* __restrict__ W) {
    __shared__ float t[32][33];
    const int blk = blockIdx.z;
    const int n0 = blockIdx.x * 32;
    const int k0 = blockIdx.y * 32;
    const int x = threadIdx.x, y = threadIdx.y;
    t[y][x] = W[((size_t)blk * DDIM + k0 + y) * DDIM + n0 + x];
    __syncthreads();
    const float v = t[x][y];   // = W[k0+x][n0+y]
    g_Wtf[((size_t)blk * DDIM + (n0 + y)) * DDIM + (k0 + x)] = __float2half_rn(v);
}

// ---------------- main kernel ----------------
__device__ __forceinline__ void load_chunk(
    uint32_t stage_base, int tid, const __half* A, const __half* B)
{
    // 1536 cp16 total: A 512 slots (128 rows x 4), B 1024 slots (256 rows x 4)
    {
        const int row = tid >> 2, c16 = tid & 3;
        cp16(stage_base + OFF_A + (uint32_t)row * ROWB + (uint32_t)c16 * 16,
             A + (size_t)row * DDIM + c16 * 8);
    }
    #pragma unroll
    for (int t = 0; t < 2; ++t) {
        const int slot = tid + t * THREADS;       // 0..1023
        const int row  = slot >> 2, c16 = slot & 3;
        cp16(stage_base + OFF_B + (uint32_t)row * ROWB + (uint32_t)c16 * 16,
             B + (size_t)row * DDIM + c16 * 8);
    }
}

__global__ void __launch_bounds__(THREADS, 1)
bs_mma_kernel(const float* __restrict__ Bv,
              const int*   __restrict__ i_idx,
              const int*   __restrict__ j_idx,
              float*       __restrict__ Y)
{
    extern __shared__ __align__(128) char smem[];
    const uint32_t sb = smem_u32(smem);

    const int tid    = threadIdx.x;
    const int wid    = tid >> 5;
    const int lane   = tid & 31;
    const int g      = lane >> 2;
    const int tg     = lane & 3;
    const int warp_m = wid >> 3;     // 0..1  (64 rows)
    const int warp_n = wid & 7;      // 0..7  (32 cols)
    const int lrow   = lane & 15;
    const int lseg   = lane >> 4;

    const int m0 = blockIdx.x * BM;
    const int ib = blockIdx.y;

    // active blocks feeding output row ib (exactly 4 by pattern construction)
    int kact[4], jact[4];
    {
        int na = 0;
        #pragma unroll 1
        for (int k = 0; k < NACT; ++k) {
            if (__ldg(i_idx + k) == ib) {
                if (na < 4) { kact[na] = k; jact[na] = __ldg(j_idx + k); }
                ++na;
            }
        }
    }

    float acc[4][4][4];
    #pragma unroll
    for (int mt = 0; mt < 4; ++mt)
        #pragma unroll
        for (int nt = 0; nt < 4; ++nt)
            #pragma unroll
            for (int q = 0; q < 4; ++q)
                acc[mt][nt][q] = 0.0f;

    auto chunk_srcs = [&](int c, const __half*& A, const __half*& B) {
        const int a  = c >> 3;
        const int kk = (c & 7) * BK;
        A = g_Xf  + ((size_t)jact[a] * BATCHN + m0) * DDIM + kk;
        B = g_Wtf + ((size_t)kact[a] * DDIM) * DDIM + kk;    // full 256-n panel
    };

    // prologue: preload NSTG-1 chunks
    #pragma unroll
    for (int c = 0; c < NSTG - 1; ++c) {
        const __half *A, *B;
        chunk_srcs(c, A, B);
        load_chunk(sb + (uint32_t)c * STAGE_BYTES, tid, A, B);
        cp_commit();
    }

    for (int c = 0; c < NCH; ++c) {
        cp_wait<NSTG - 2>();          // chunk c resident
        __syncthreads();              // protects reuse of stage (c-1)%NSTG

        if (c + NSTG - 1 < NCH) {
            const __half *A, *B;
            chunk_srcs(c + NSTG - 1, A, B);
            load_chunk(sb + (uint32_t)((c + NSTG - 1) % NSTG) * STAGE_BYTES, tid, A, B);
            cp_commit();
        } else {
            cp_commit();              // keep group accounting aligned
        }

        const uint32_t st = sb + (uint32_t)(c % NSTG) * STAGE_BYTES;
        const uint32_t aB = st + OFF_A, bB = st + OFF_B;

        #pragma unroll
        for (int ks = 0; ks < BK; ks += 16) {
            const uint32_t fcol = (uint32_t)(ks * 2 + lseg * 16);
            const uint32_t bo = (uint32_t)(warp_n * 32 + lrow) * ROWB + fcol;
            uint32_t b0[4], b1[4];
            ldsm4(b0, bB + bo);
            ldsm4(b1, bB + bo + 16 * ROWB);

            #pragma unroll
            for (int mt = 0; mt < 4; ++mt) {
                const uint32_t ao =
                    (uint32_t)(warp_m * 64 + mt * 16 + lrow) * ROWB + fcol;
                uint32_t a[4];
                ldsm4(a, aB + ao);
                mma_f16(acc[mt][0], a, b0[0], b0[2]);
                mma_f16(acc[mt][1], a, b0[1], b0[3]);
                mma_f16(acc[mt][2], a, b1[0], b1[2]);
                mma_f16(acc[mt][3], a, b1[1], b1[3]);
            }
        }
    }

    // bias sums for all 256 output cols
    __syncthreads();
    if (tid < DDIM) {
        float bs = __ldg(Bv + (size_t)kact[0] * DDIM + tid)
                 + __ldg(Bv + (size_t)kact[1] * DDIM + tid)
                 + __ldg(Bv + (size_t)kact[2] * DDIM + tid)
                 + __ldg(Bv + (size_t)kact[3] * DDIM + tid);
        reinterpret_cast<float*>(smem + SM_BIAS)[tid] = bs;
    }
    __syncthreads();
    const float* biasp = reinterpret_cast<const float*>(smem + SM_BIAS);

    // epilogue: each element written exactly once
    #pragma unroll
    for (int mt = 0; mt < 4; ++mt) {
        const int row = m0 + warp_m * 64 + mt * 16 + g;
        #pragma unroll
        for (int nt = 0; nt < 4; ++nt) {
            const int col = warp_n * 32 + nt * 8 + tg * 2;
            const float b0 = biasp[col], b1 = biasp[col + 1];
            const size_t o0 = ((size_t)ib * BATCHN + row) * DDIM + col;
            const size_t o1 = o0 + (size_t)8 * DDIM;
            *reinterpret_cast<float2*>(Y + o0) =
                make_float2(acc[mt][nt][0] + b0, acc[mt][nt][1] + b1);
            *reinterpret_cast<float2*>(Y + o1) =
                make_float2(acc[mt][nt][2] + b0, acc[mt][nt][3] + b1);
        }
    }
}

} // namespace

extern "C" void kernel_launch(void* const* d_in, const int* in_sizes, int n_in,
                              void* d_out, int out_size) {
    const float* X     = (const float*)d_in[0];
    const float* W     = (const float*)d_in[1];
    const float* b     = (const float*)d_in[2];
    const int*   i_idx = (const int*)d_in[3];
    const int*   j_idx = (const int*)d_in[4];
    float*       Y     = (float*)d_out;

    cudaFuncSetAttribute(bs_mma_kernel,
                         cudaFuncAttributeMaxDynamicSharedMemorySize, SMEM_TOTAL);

    const int x4 = NBLK * BATCHN * DDIM / 4;
    conv_x_kernel<<<x4 / 256, 256>>>(X);
    conv_w_kernel<<<dim3(DDIM / 32, DDIM / 32, NACT), dim3(32, 32)>>>(W);

    bs_mma_kernel<<<dim3(BATCHN / BM, NBLK), THREADS, SMEM_TOTAL>>>(
        b, i_idx, j_idx, Y);
}

// round 6
// speedup vs baseline: 1.2469x; 1.2469x over previous
#include <cuda_runtime.h>
#include <cuda_fp16.h>
#include <cstdint>

// Block-sparse batched linear (sm_103 family-safe: mma.sync + ldmatrix):
//   Y[i] = sum_{k: i_idx[k]==i} ( X[j_idx[k]] @ W[k] + b[k] )
// Prep: X -> fp16; W -> transposed [n][k] fp16.
// Main: CTA 128x128, BK=64, 8 warps (2x4, 64x32 warp tiles), single-pass
// fp16 mma.sync.m16n8k16 w/ f32 accum, ldmatrix.x4 feeds, 3-stage cp.async
// pipeline (16 chunks -> half the barrier frequency of round 4), 2 CTAs/SM.

namespace {

constexpr int NBLK   = 12;
constexpr int DDIM   = 256;
constexpr int BATCHN = 8192;
constexpr int NACT   = 48;

constexpr int BM = 128;
constexpr int BN = 128;
constexpr int BK = 64;
constexpr int NCH = 16;          // 4 active blocks * 4 k-chunks
constexpr int NSTG = 3;
constexpr int THREADS = 256;

constexpr uint32_t ROWB  = 144;           // 128B data + 16B pad per 64-elem row
constexpr uint32_t ASZ   = 128 * ROWB;    // 18432 B per operand tile
constexpr uint32_t OFF_A = 0;
constexpr uint32_t OFF_B = ASZ;
constexpr uint32_t STAGE_BYTES = 2 * ASZ;                  // 36864
constexpr uint32_t SM_BIAS     = NSTG * STAGE_BYTES;       // 110592
constexpr uint32_t SMEM_TOTAL  = SM_BIAS + 128 * 4;        // 111104 (2 CTAs/SM ok)

// ---- device scratch (static; no runtime allocation) ----
__device__ __half g_Xf[(size_t)NBLK * BATCHN * DDIM];
__device__ __half g_Wtf[(size_t)NACT * DDIM * DDIM];   // [blk][n][k]

// ---------------- helpers ----------------
__device__ __forceinline__ uint32_t smem_u32(const void* p) {
    uint32_t a;
    asm("{ .reg .u64 t; cvta.to.shared.u64 t, %1; cvt.u32.u64 %0, t; }"
        : "=r"(a) : "l"(p));
    return a;
}
__device__ __forceinline__ void cp16(uint32_t dst, const void* src) {
    asm volatile("cp.async.cg.shared.global [%0], [%1], 16;\n" :: "r"(dst), "l"(src));
}
__device__ __forceinline__ void cp_commit() { asm volatile("cp.async.commit_group;\n"); }
template <int N>
__device__ __forceinline__ void cp_wait() { asm volatile("cp.async.wait_group %0;\n" :: "n"(N)); }

__device__ __forceinline__ void ldsm4(uint32_t r[4], uint32_t addr) {
    asm volatile("ldmatrix.sync.aligned.m8n8.x4.shared.b16 {%0,%1,%2,%3}, [%4];"
                 : "=r"(r[0]), "=r"(r[1]), "=r"(r[2]), "=r"(r[3]) : "r"(addr));
}
__device__ __forceinline__ void mma_f16(float d[4], const uint32_t a[4],
                                        uint32_t b0, uint32_t b1) {
    asm volatile(
        "mma.sync.aligned.m16n8k16.row.col.f32.f16.f16.f32 "
        "{%0,%1,%2,%3}, {%4,%5,%6,%7}, {%8,%9}, {%0,%1,%2,%3};\n"
        : "+f"(d[0]), "+f"(d[1]), "+f"(d[2]), "+f"(d[3])
        : "r"(a[0]), "r"(a[1]), "r"(a[2]), "r"(a[3]), "r"(b0), "r"(b1));
}

// ---------------- prep kernels ----------------
__global__ void __launch_bounds__(256) conv_x_kernel(const float* __restrict__ X) {
    size_t i = (size_t)blockIdx.x * blockDim.x + threadIdx.x;  // float4 slot
    const float4 v = reinterpret_cast<const float4*>(X)[i];
    __half2 p0 = __floats2half2_rn(v.x, v.y);
    __half2 p1 = __floats2half2_rn(v.z, v.w);
    reinterpret_cast<uint2*>(g_Xf)[i] =
        make_uint2(*reinterpret_cast<uint32_t*>(&p0), *reinterpret_cast<uint32_t*>(&p1));
}

__global__ void __launch_bounds__(1024) conv_w_kernel(const float* __restrict__ W) {
    __shared__ float t[32][33];
    const int blk = blockIdx.z;
    const int n0 = blockIdx.x * 32;
    const int k0 = blockIdx.y * 32;
    const int x = threadIdx.x, y = threadIdx.y;
    t[y][x] = W[((size_t)blk * DDIM + k0 + y) * DDIM + n0 + x];
    __syncthreads();
    const float v = t[x][y];   // = W[k0+x][n0+y]
    g_Wtf[((size_t)blk * DDIM + (n0 + y)) * DDIM + (k0 + x)] = __float2half_rn(v);
}

// ---------------- main kernel ----------------
__device__ __forceinline__ void load_chunk(
    uint32_t stage_base, int tid, const __half* A, const __half* B)
{
    // per array: 128 rows x 8 chunks of 16B = 1024 slots; 4 per thread
    #pragma unroll
    for (int t = 0; t < 4; ++t) {
        const int slot = tid + t * THREADS;       // 0..1023
        const int row  = slot >> 3;               // 0..127
        const int c16  = slot & 7;                // 16B chunk within 128B row
        const uint32_t dst = (uint32_t)row * ROWB + (uint32_t)c16 * 16;
        const size_t   so  = (size_t)row * DDIM + c16 * 8;
        cp16(stage_base + OFF_A + dst, A + so);
        cp16(stage_base + OFF_B + dst, B + so);
    }
}

__global__ void __launch_bounds__(THREADS, 2)
bs_mma_kernel(const float* __restrict__ Bv,
              const int*   __restrict__ i_idx,
              const int*   __restrict__ j_idx,
              float*       __restrict__ Y)
{
    extern __shared__ __align__(128) char smem[];
    const uint32_t sb = smem_u32(smem);

    const int tid    = threadIdx.x;
    const int wid    = tid >> 5;
    const int lane   = tid & 31;
    const int g      = lane >> 2;
    const int tg     = lane & 3;
    const int warp_m = wid >> 2;     // 0..1  (64 rows)
    const int warp_n = wid & 3;      // 0..3  (32 cols)
    const int lrow   = lane & 15;
    const int lseg   = lane >> 4;

    const int m0 = blockIdx.x * BM;
    const int n0 = blockIdx.y * BN;
    const int ib = blockIdx.z;

    // active blocks feeding output row ib (exactly 4 by pattern construction)
    int kact[4], jact[4];
    {
        int na = 0;
        #pragma unroll 1
        for (int k = 0; k < NACT; ++k) {
            if (__ldg(i_idx + k) == ib) {
                if (na < 4) { kact[na] = k; jact[na] = __ldg(j_idx + k); }
                ++na;
            }
        }
    }

    float acc[4][4][4];
    #pragma unroll
    for (int mt = 0; mt < 4; ++mt)
        #pragma unroll
        for (int nt = 0; nt < 4; ++nt)
            #pragma unroll
            for (int q = 0; q < 4; ++q)
                acc[mt][nt][q] = 0.0f;

    auto chunk_srcs = [&](int c, const __half*& A, const __half*& B) {
        const int a  = c >> 2;
        const int kk = (c & 3) * BK;
        A = g_Xf  + ((size_t)jact[a] * BATCHN + m0) * DDIM + kk;
        B = g_Wtf + ((size_t)kact[a] * DDIM + n0) * DDIM + kk;
    };

    // prologue: preload NSTG-1 = 2 chunks
    #pragma unroll
    for (int c = 0; c < NSTG - 1; ++c) {
        const __half *A, *B;
        chunk_srcs(c, A, B);
        load_chunk(sb + (uint32_t)c * STAGE_BYTES, tid, A, B);
        cp_commit();
    }

    for (int c = 0; c < NCH; ++c) {
        cp_wait<NSTG - 2>();          // chunk c resident
        __syncthreads();              // protects reuse of stage (c-1)%NSTG

        if (c + NSTG - 1 < NCH) {     // load chunk c+2 into stage (c+2)%3 = (c-1)%3
            const __half *A, *B;
            chunk_srcs(c + NSTG - 1, A, B);
            load_chunk(sb + (uint32_t)((c + NSTG - 1) % NSTG) * STAGE_BYTES, tid, A, B);
            cp_commit();
        } else {
            cp_commit();              // keep group accounting aligned
        }

        const uint32_t st = sb + (uint32_t)(c % NSTG) * STAGE_BYTES;
        const uint32_t aB = st + OFF_A, bB = st + OFF_B;

        #pragma unroll
        for (int ks = 0; ks < BK; ks += 16) {
            const uint32_t fcol = (uint32_t)(ks * 2 + lseg * 16);
            const uint32_t bo = (uint32_t)(warp_n * 32 + lrow) * ROWB + fcol;
            uint32_t b0[4], b1[4];
            ldsm4(b0, bB + bo);
            ldsm4(b1, bB + bo + 16 * ROWB);

            #pragma unroll
            for (int mt = 0; mt < 4; ++mt) {
                const uint32_t ao =
                    (uint32_t)(warp_m * 64 + mt * 16 + lrow) * ROWB + fcol;
                uint32_t a[4];
                ldsm4(a, aB + ao);
                mma_f16(acc[mt][0], a, b0[0], b0[2]);
                mma_f16(acc[mt][1], a, b0[1], b0[3]);
                mma_f16(acc[mt][2], a, b1[0], b1[2]);
                mma_f16(acc[mt][3], a, b1[1], b1[3]);
            }
        }
    }

    // bias sums for this CTA's 128 output cols
    __syncthreads();
    if (tid < BN) {
        const int col = n0 + tid;
        float bs = __ldg(Bv + (size_t)kact[0] * DDIM + col)
                 + __ldg(Bv + (size_t)kact[1] * DDIM + col)
                 + __ldg(Bv + (size_t)kact[2] * DDIM + col)
                 + __ldg(Bv + (size_t)kact[3] * DDIM + col);
        reinterpret_cast<float*>(smem + SM_BIAS)[tid] = bs;
    }
    __syncthreads();
    const float* biasp = reinterpret_cast<const float*>(smem + SM_BIAS);

    // epilogue: each element written exactly once
    #pragma unroll
    for (int mt = 0; mt < 4; ++mt) {
        const int row = m0 + warp_m * 64 + mt * 16 + g;
        #pragma unroll
        for (int nt = 0; nt < 4; ++nt) {
            const int lc  = warp_n * 32 + nt * 8 + tg * 2;
            const float b0 = biasp[lc], b1 = biasp[lc + 1];
            const size_t o0 = ((size_t)ib * BATCHN + row) * DDIM + n0 + lc;
            const size_t o1 = o0 + (size_t)8 * DDIM;
            *reinterpret_cast<float2*>(Y + o0) =
                make_float2(acc[mt][nt][0] + b0, acc[mt][nt][1] + b1);
            *reinterpret_cast<float2*>(Y + o1) =
                make_float2(acc[mt][nt][2] + b0, acc[mt][nt][3] + b1);
        }
    }
}

} // namespace

extern "C" void kernel_launch(void* const* d_in, const int* in_sizes, int n_in,
                              void* d_out, int out_size) {
    const float* X     = (const float*)d_in[0];
    const float* W     = (const float*)d_in[1];
    const float* b     = (const float*)d_in[2];
    const int*   i_idx = (const int*)d_in[3];
    const int*   j_idx = (const int*)d_in[4];
    float*       Y     = (float*)d_out;

    cudaFuncSetAttribute(bs_mma_kernel,
                         cudaFuncAttributeMaxDynamicSharedMemorySize, SMEM_TOTAL);

    const int x4 = NBLK * BATCHN * DDIM / 4;
    conv_x_kernel<<<x4 / 256, 256>>>(X);
    conv_w_kernel<<<dim3(DDIM / 32, DDIM / 32, NACT), dim3(32, 32)>>>(W);

    bs_mma_kernel<<<dim3(BATCHN / BM, DDIM / BN, NBLK), THREADS, SMEM_TOTAL>>>(
        b, i_idx, j_idx, Y);
}

// round 8
// speedup vs baseline: 1.6764x; 1.3444x over previous
#include <cuda_runtime.h>
#include <cuda_fp16.h>
#include <cstdint>

// Block-sparse batched linear (sm_103 family-safe: mma.sync + ldmatrix):
//   Y[i] = sum_{k: i_idx[k]==i} ( X[j_idx[k]] @ W[k] + b[k] )
// Prep: X -> fp16; W -> transposed [n][k] fp16.
// Main: CTA 128x128, 4 warps (2x2 grid, 64x64 warp tiles -> MMA:LDSM 4.0),
// single-pass fp16 mma.sync.m16n8k16 w/ f32 accum, ldmatrix.x4 feeds,
// 4-stage cp.async pipeline (BK=32, wait<2>), 2 CTAs/SM.

namespace {

constexpr int NBLK   = 12;
constexpr int DDIM   = 256;
constexpr int BATCHN = 8192;
constexpr int NACT   = 48;

constexpr int BM = 128;
constexpr int BN = 128;
constexpr int BK = 32;
constexpr int NCH = 32;          // 4 active blocks * 8 k-chunks
constexpr int NSTG = 4;
constexpr int THREADS = 128;

constexpr uint32_t ROWB  = 80;            // 64B data + 16B pad per 32-elem row
constexpr uint32_t ASZ   = 128 * ROWB;    // 10240 B per operand tile
constexpr uint32_t OFF_A = 0;
constexpr uint32_t OFF_B = ASZ;
constexpr uint32_t STAGE_BYTES = 2 * ASZ;                  // 20480
constexpr uint32_t SM_BIAS     = NSTG * STAGE_BYTES;       // 81920
constexpr uint32_t SMEM_TOTAL  = SM_BIAS + 128 * 4;        // 82432

// ---- device scratch (static; no runtime allocation) ----
__device__ __half g_Xf[(size_t)NBLK * BATCHN * DDIM];
__device__ __half g_Wtf[(size_t)NACT * DDIM * DDIM];   // [blk][n][k]

// ---------------- helpers ----------------
__device__ __forceinline__ uint32_t smem_u32(const void* p) {
    uint32_t a;
    asm("{ .reg .u64 t; cvta.to.shared.u64 t, %1; cvt.u32.u64 %0, t; }"
        : "=r"(a) : "l"(p));
    return a;
}
__device__ __forceinline__ void cp16(uint32_t dst, const void* src) {
    asm volatile("cp.async.cg.shared.global [%0], [%1], 16;\n" :: "r"(dst), "l"(src));
}
__device__ __forceinline__ void cp_commit() { asm volatile("cp.async.commit_group;\n"); }
template <int N>
__device__ __forceinline__ void cp_wait() { asm volatile("cp.async.wait_group %0;\n" :: "n"(N)); }

__device__ __forceinline__ void ldsm4(uint32_t r[4], uint32_t addr) {
    asm volatile("ldmatrix.sync.aligned.m8n8.x4.shared.b16 {%0,%1,%2,%3}, [%4];"
                 : "=r"(r[0]), "=r"(r[1]), "=r"(r[2]), "=r"(r[3]) : "r"(addr));
}
__device__ __forceinline__ void mma_f16(float d[4], const uint32_t a[4],
                                        uint32_t b0, uint32_t b1) {
    asm volatile(
        "mma.sync.aligned.m16n8k16.row.col.f32.f16.f16.f32 "
        "{%0,%1,%2,%3}, {%4,%5,%6,%7}, {%8,%9}, {%0,%1,%2,%3};\n"
        : "+f"(d[0]), "+f"(d[1]), "+f"(d[2]), "+f"(d[3])
        : "r"(a[0]), "r"(a[1]), "r"(a[2]), "r"(a[3]), "r"(b0), "r"(b1));
}

// ---------------- prep kernels ----------------
__global__ void __launch_bounds__(256) conv_x_kernel(const float* __restrict__ X) {
    size_t i = (size_t)blockIdx.x * blockDim.x + threadIdx.x;  // float4 slot
    const float4 v = reinterpret_cast<const float4*>(X)[i];
    __half2 p0 = __floats2half2_rn(v.x, v.y);
    __half2 p1 = __floats2half2_rn(v.z, v.w);
    reinterpret_cast<uint2*>(g_Xf)[i] =
        make_uint2(*reinterpret_cast<uint32_t*>(&p0), *reinterpret_cast<uint32_t*>(&p1));
}

__global__ void __launch_bounds__(1024) conv_w_kernel(const float* __restrict__ W) {
    __shared__ float t[32][33];
    const int blk = blockIdx.z;
    const int n0 = blockIdx.x * 32;
    const int k0 = blockIdx.y * 32;
    const int x = threadIdx.x, y = threadIdx.y;
    t[y][x] = W[((size_t)blk * DDIM + k0 + y) * DDIM + n0 + x];
    __syncthreads();
    const float v = t[x][y];   // = W[k0+x][n0+y]
    g_Wtf[((size_t)blk * DDIM + (n0 + y)) * DDIM + (k0 + x)] = __float2half_rn(v);
}

// ---------------- main kernel ----------------
__device__ __forceinline__ void load_chunk(
    uint32_t stage_base, int tid, const __half* A, const __half* B)
{
    // per array: 128 rows x 4 chunks of 16B = 512 slots; 4 per thread
    #pragma unroll
    for (int t = 0; t < 4; ++t) {
        const int slot = tid + t * THREADS;       // 0..511
        const int row  = slot >> 2;               // 0..127
        const int c16  = slot & 3;                // 16B chunk within 64B row
        const uint32_t dst = (uint32_t)row * ROWB + (uint32_t)c16 * 16;
        const size_t   so  = (size_t)row * DDIM + c16 * 8;
        cp16(stage_base + OFF_A + dst, A + so);
        cp16(stage_base + OFF_B + dst, B + so);
    }
}

__global__ void __launch_bounds__(THREADS, 2)
bs_mma_kernel(const float* __restrict__ Bv,
              const int*   __restrict__ i_idx,
              const int*   __restrict__ j_idx,
              float*       __restrict__ Y)
{
    extern __shared__ __align__(128) char smem[];
    const uint32_t sb = smem_u32(smem);

    const int tid    = threadIdx.x;
    const int wid    = tid >> 5;
    const int lane   = tid & 31;
    const int g      = lane >> 2;
    const int tg     = lane & 3;
    const int warp_m = wid >> 1;     // 0..1  (64 rows)
    const int warp_n = wid & 1;      // 0..1  (64 cols)
    const int lrow   = lane & 15;
    const int lseg   = lane >> 4;

    const int m0 = blockIdx.x * BM;
    const int n0 = blockIdx.y * BN;
    const int ib = blockIdx.z;

    // active blocks feeding output row ib (exactly 4 by pattern construction)
    int kact[4], jact[4];
    {
        int na = 0;
        #pragma unroll 1
        for (int k = 0; k < NACT; ++k) {
            if (__ldg(i_idx + k) == ib) {
                if (na < 4) { kact[na] = k; jact[na] = __ldg(j_idx + k); }
                ++na;
            }
        }
    }

    // 64x64 warp tile: acc[mt 0..3][nt 0..7][4]
    float acc[4][8][4];
    #pragma unroll
    for (int mt = 0; mt < 4; ++mt)
        #pragma unroll
        for (int nt = 0; nt < 8; ++nt)
            #pragma unroll
            for (int q = 0; q < 4; ++q)
                acc[mt][nt][q] = 0.0f;

    auto chunk_srcs = [&](int c, const __half*& A, const __half*& B) {
        const int a  = c >> 3;
        const int kk = (c & 7) * BK;
        A = g_Xf  + ((size_t)jact[a] * BATCHN + m0) * DDIM + kk;
        B = g_Wtf + ((size_t)kact[a] * DDIM + n0) * DDIM + kk;
    };

    // prologue: preload NSTG-1 = 3 chunks
    #pragma unroll
    for (int c = 0; c < NSTG - 1; ++c) {
        const __half *A, *B;
        chunk_srcs(c, A, B);
        load_chunk(sb + (uint32_t)c * STAGE_BYTES, tid, A, B);
        cp_commit();
    }

    for (int c = 0; c < NCH; ++c) {
        cp_wait<NSTG - 2>();          // chunk c resident
        __syncthreads();              // protects reuse of stage (c-1)%NSTG

        if (c + NSTG - 1 < NCH) {
            const __half *A, *B;
            chunk_srcs(c + NSTG - 1, A, B);
            load_chunk(sb + (uint32_t)((c + NSTG - 1) % NSTG) * STAGE_BYTES, tid, A, B);
            cp_commit();
        } else {
            cp_commit();              // keep group accounting aligned
        }

        const uint32_t st = sb + (uint32_t)(c % NSTG) * STAGE_BYTES;
        const uint32_t aB = st + OFF_A, bB = st + OFF_B;

        #pragma unroll
        for (int ks = 0; ks < BK; ks += 16) {
            const uint32_t fcol = (uint32_t)(ks * 2 + lseg * 16);
            // B fragments: 4 x ldsm.x4 covering 64 n-cols
            const uint32_t bo = (uint32_t)(warp_n * 64 + lrow) * ROWB + fcol;
            uint32_t b[4][4];
            ldsm4(b[0], bB + bo);
            ldsm4(b[1], bB + bo + 16 * ROWB);
            ldsm4(b[2], bB + bo + 32 * ROWB);
            ldsm4(b[3], bB + bo + 48 * ROWB);

            #pragma unroll
            for (int mt = 0; mt < 4; ++mt) {
                const uint32_t ao =
                    (uint32_t)(warp_m * 64 + mt * 16 + lrow) * ROWB + fcol;
                uint32_t a[4];
                ldsm4(a, aB + ao);
                #pragma unroll
                for (int t = 0; t < 4; ++t) {
                    mma_f16(acc[mt][t * 2 + 0], a, b[t][0], b[t][2]);
                    mma_f16(acc[mt][t * 2 + 1], a, b[t][1], b[t][3]);
                }
            }
        }
    }

    // bias sums for this CTA's 128 output cols
    __syncthreads();
    if (tid < BN) {
        const int col = n0 + tid;
        float bs = __ldg(Bv + (size_t)kact[0] * DDIM + col)
                 + __ldg(Bv + (size_t)kact[1] * DDIM + col)
                 + __ldg(Bv + (size_t)kact[2] * DDIM + col)
                 + __ldg(Bv + (size_t)kact[3] * DDIM + col);
        reinterpret_cast<float*>(smem + SM_BIAS)[tid] = bs;
    }
    __syncthreads();
    const float* biasp = reinterpret_cast<const float*>(smem + SM_BIAS);

    // epilogue: each element written exactly once
    #pragma unroll
    for (int mt = 0; mt < 4; ++mt) {
        const int row = m0 + warp_m * 64 + mt * 16 + g;
        #pragma unroll
        for (int nt = 0; nt < 8; ++nt) {
            const int lc  = warp_n * 64 + nt * 8 + tg * 2;
            const float b0 = biasp[lc], b1 = biasp[lc + 1];
            const size_t o0 = ((size_t)ib * BATCHN + row) * DDIM + n0 + lc;
            const size_t o1 = o0 + (size_t)8 * DDIM;
            *reinterpret_cast<float2*>(Y + o0) =
                make_float2(acc[mt][nt][0] + b0, acc[mt][nt][1] + b1);
            *reinterpret_cast<float2*>(Y + o1) =
                make_float2(acc[mt][nt][2] + b0, acc[mt][nt][3] + b1);
        }
    }
}

} // namespace

extern "C" void kernel_launch(void* const* d_in, const int* in_sizes, int n_in,
                              void* d_out, int out_size) {
    const float* X     = (const float*)d_in[0];
    const float* W     = (const float*)d_in[1];
    const float* b     = (const float*)d_in[2];
    const int*   i_idx = (const int*)d_in[3];
    const int*   j_idx = (const int*)d_in[4];
    float*       Y     = (float*)d_out;

    cudaFuncSetAttribute(bs_mma_kernel,
                         cudaFuncAttributeMaxDynamicSharedMemorySize, SMEM_TOTAL);

    const int x4 = NBLK * BATCHN * DDIM / 4;
    conv_x_kernel<<<x4 / 256, 256>>>(X);
    conv_w_kernel<<<dim3(DDIM / 32, DDIM / 32, NACT), dim3(32, 32)>>>(W);

    bs_mma_kernel<<<dim3(BATCHN / BM, DDIM / BN, NBLK), THREADS, SMEM_TOTAL>>>(
        b, i_idx, j_idx, Y);
}